// round 16
// baseline (speedup 1.0000x reference)
#include <cuda_runtime.h>
#include <cuda_bf16.h>
#include <cstdint>

#define HEADS 16
#define NW 64
#define CH 256
#define PA 264      // pitch (halves) bf16 activation buffers [64 x 256]
#define PQK 24      // pitch (halves) q/k head tiles [64 x 16]
#define PVT 72      // pitch (halves) vT head tiles [16 x 64]
#define LOG2E 1.4426950408889634f

// smem float offsets
#define OFF_AN 0        // s_an: bf16 [64][264] = 8448 fl
#define OFF_AB 8448     // s_ab: bf16 [64][264] = 8448 fl
#define OFF_R  16896    // tiles q/k/vT (16896h = 33792B); aliased as cp.async B staging in mainloops
#define OFF_MI 25344    // s_m[64], s_i[64]
#define OFF_RED 25472   // s_red float2[64][4] = 512 fl
#define SMEM_FLOATS 25984

__device__ uint2 g_biasf[HEADS * 4 * 8 * 32];       // [h][rowtile(4)][j(8)][lane] C-frag bias (x log2e)
__device__ uint4 g_wqf4[4 * 8 * 2 * 4 * 3 * 32];    // [p][kb][ks][nh4][jp][lane] B-fragment pairs
__device__ uint4 g_wpf4[16 * 4 * 4 * 32];           // [kb][nh4][jp][lane] B-fragment pairs

__device__ __forceinline__ uint32_t pk2(float lo, float hi) {
    __nv_bfloat162 h = __floats2bfloat162_rn(lo, hi);
    return *(uint32_t*)&h;
}
__global__ void prep_bias_frag(const float* __restrict__ table,
                               const int* __restrict__ ridx) {
    int t = blockIdx.x * blockDim.x + threadIdx.x;
    if (t >= 16384) return;
    int lane = t & 31;
    int r = t >> 5;
    int j = r & 7; r >>= 3;
    int rt = r & 3; r >>= 2;
    int h = r;
    int g = lane >> 2, tq = (lane & 3) * 2;
    int row0 = rt * 16 + g, row1 = row0 + 8, col = j * 8 + tq;
    float b00 = table[ridx[row0 * 64 + col] * HEADS + h] * LOG2E;
    float b01 = table[ridx[row0 * 64 + col + 1] * HEADS + h] * LOG2E;
    float b10 = table[ridx[row1 * 64 + col] * HEADS + h] * LOG2E;
    float b11 = table[ridx[row1 * 64 + col + 1] * HEADS + h] * LOG2E;
    uint2 v;
    v.x = pk2(b00, b01);
    v.y = pk2(b10, b11);
    g_biasf[t] = v;
}
__global__ void prep_wq_frag4(const float* __restrict__ qkv_w) {
    int t = blockIdx.x * blockDim.x + threadIdx.x;
    if (t >= 24576) return;
    int lane = t & 31;
    int r = t >> 5;
    int jp = r % 3; r /= 3;
    int nh4 = r & 3; r >>= 2;
    int ks = r & 1; r >>= 1;
    int kb = r & 7; r >>= 3;
    int p = r;
    int g = lane >> 2, tq = (lane & 3) * 2;
    int k0 = kb * 32 + ks * 16 + tq;
    uint4 v;
    {
        int n = nh4 * 48 + (2 * jp) * 8 + g;
        int gcol = (n >> 6) * 256 + p * 64 + (n & 63);
        v.x = pk2(qkv_w[(size_t)k0 * 768 + gcol],       qkv_w[(size_t)(k0 + 1) * 768 + gcol]);
        v.y = pk2(qkv_w[(size_t)(k0 + 8) * 768 + gcol], qkv_w[(size_t)(k0 + 9) * 768 + gcol]);
    }
    {
        int n = nh4 * 48 + (2 * jp + 1) * 8 + g;
        int gcol = (n >> 6) * 256 + p * 64 + (n & 63);
        v.z = pk2(qkv_w[(size_t)k0 * 768 + gcol],       qkv_w[(size_t)(k0 + 1) * 768 + gcol]);
        v.w = pk2(qkv_w[(size_t)(k0 + 8) * 768 + gcol], qkv_w[(size_t)(k0 + 9) * 768 + gcol]);
    }
    g_wqf4[t] = v;
}
__global__ void prep_wp_frag4(const float* __restrict__ proj_w) {
    int t = blockIdx.x * blockDim.x + threadIdx.x;
    if (t >= 8192) return;
    int lane = t & 31;
    int r = t >> 5;
    int jp = r & 3; r >>= 2;
    int nh4 = r & 3; r >>= 2;
    int kb = r;
    int g = lane >> 2, tq = (lane & 3) * 2;
    int k0 = kb * 16 + tq;
    uint4 v;
    {
        int n = nh4 * 64 + (2 * jp) * 8 + g;
        v.x = pk2(proj_w[(size_t)k0 * 256 + n],       proj_w[(size_t)(k0 + 1) * 256 + n]);
        v.y = pk2(proj_w[(size_t)(k0 + 8) * 256 + n], proj_w[(size_t)(k0 + 9) * 256 + n]);
    }
    {
        int n = nh4 * 64 + (2 * jp + 1) * 8 + g;
        v.z = pk2(proj_w[(size_t)k0 * 256 + n],       proj_w[(size_t)(k0 + 1) * 256 + n]);
        v.w = pk2(proj_w[(size_t)(k0 + 8) * 256 + n], proj_w[(size_t)(k0 + 9) * 256 + n]);
    }
    g_wpf4[t] = v;
}

__device__ __forceinline__ uint32_t SAu(const void* p) {
    return (uint32_t)__cvta_generic_to_shared(p);
}
__device__ __forceinline__ void cp16s(void* dst, const void* src) {
    uint32_t d = (uint32_t)__cvta_generic_to_shared(dst);
    asm volatile("cp.async.cg.shared.global [%0], [%1], 16;" :: "r"(d), "l"(src) : "memory");
}
__device__ __forceinline__ void cp_commit() { asm volatile("cp.async.commit_group;" ::: "memory"); }
__device__ __forceinline__ void cp_wait1()  { asm volatile("cp.async.wait_group 1;" ::: "memory"); }
__device__ __forceinline__ void cp_wait0()  { asm volatile("cp.async.wait_group 0;" ::: "memory"); }
__device__ __forceinline__ void ldsm4(uint32_t* r, uint32_t a) {
    asm volatile("ldmatrix.sync.aligned.m8n8.x4.shared.b16 {%0,%1,%2,%3}, [%4];"
        : "=r"(r[0]), "=r"(r[1]), "=r"(r[2]), "=r"(r[3]) : "r"(a));
}
__device__ __forceinline__ void stsm4(uint32_t a, uint32_t r0, uint32_t r1,
                                      uint32_t r2, uint32_t r3) {
    asm volatile("stmatrix.sync.aligned.m8n8.x4.shared.b16 [%0], {%1,%2,%3,%4};"
        :: "r"(a), "r"(r0), "r"(r1), "r"(r2), "r"(r3) : "memory");
}
__device__ __forceinline__ void mma16816(float* c, uint32_t a0, uint32_t a1,
                                         uint32_t a2, uint32_t a3,
                                         uint32_t b0, uint32_t b1) {
    asm volatile("mma.sync.aligned.m16n8k16.row.col.f32.bf16.bf16.f32 "
        "{%0,%1,%2,%3}, {%4,%5,%6,%7}, {%8,%9}, {%0,%1,%2,%3};"
        : "+f"(c[0]), "+f"(c[1]), "+f"(c[2]), "+f"(c[3])
        : "r"(a0), "r"(a1), "r"(a2), "r"(a3), "r"(b0), "r"(b1));
}
__device__ __forceinline__ uint32_t pack2(float lo, float hi) {
    __nv_bfloat162 h = __floats2bfloat162_rn(lo, hi);
    return *(uint32_t*)&h;
}
__device__ __forceinline__ float2 unpack2(uint32_t u) {
    __nv_bfloat162 h = *(__nv_bfloat162*)&u;
    return make_float2(__bfloat162float(h.x), __bfloat162float(h.y));
}
__device__ __forceinline__ uint16_t bfr(float v) {
    __nv_bfloat16 h = __float2bfloat16(v);
    return *(uint16_t*)&h;
}
__device__ __forceinline__ float ex2f(float x) {
    float y;
    asm("ex2.approx.ftz.f32 %0, %1;" : "=f"(y) : "f"(x));
    return y;
}

__global__ __launch_bounds__(256, 2)
void window_attn_kernel(const float* __restrict__ X,
                        const float* __restrict__ pre_g, const float* __restrict__ pre_b,
                        const float* __restrict__ post_g, const float* __restrict__ post_b,
                        const float* __restrict__ qkv_b, const float* __restrict__ proj_b,
                        float* __restrict__ out) {
    extern __shared__ float sm[];
    uint16_t*  s_an = (uint16_t*)(sm + OFF_AN);
    uint16_t*  s_ab = (uint16_t*)(sm + OFF_AB);
    uint16_t*  s_R  = (uint16_t*)(sm + OFF_R);
    uint16_t*  s_qt = s_R;                 // [4][64][24]
    uint16_t*  s_kt = s_R + 6144;          // [4][64][24]
    uint16_t*  s_vt = s_R + 12288;         // [4][16][72]
    char*      stg  = (char*)s_R;          // B staging, aliases tiles (dead in mainloops)
    float*     s_m  = sm + OFF_MI;
    float*     s_i  = sm + OFF_MI + 64;
    float2 (*s_red)[4] = (float2(*)[4])(sm + OFF_RED);

    const uint32_t an_b = SAu(s_an);
    const uint32_t ab_b = SAu(s_ab);
    const uint32_t qt_b = SAu(s_qt);
    const uint32_t kt_b = SAu(s_kt);
    const uint32_t vt_b = SAu(s_vt);

    const int w    = blockIdx.x;
    const int b    = w >> 10;
    const int hi   = (w >> 5) & 31;
    const int wi   = w & 31;
    const int tid  = threadIdx.x;
    const int lane = tid & 31;
    const int warp = tid >> 5;

    const float* Xb = X + (size_t)b * (CH * 65536) + hi * 8 * 256 + wi * 8;
    float*       Ob = out + (size_t)b * (CH * 65536) + hi * 8 * 256 + wi * 8;

    // ---------- phase 0: pre-LN from global, X kept in registers ----------
    {
        const int n0 = tid >> 2;
        const int cb = tid & 3;
        float v[64];
        float s = 0.f, s2 = 0.f;
        const float* Xt = Xb + (n0 >> 3) * 256 + (n0 & 7);
        #pragma unroll
        for (int i = 0; i < 64; i++) {
            v[i] = Xt[(size_t)(cb + 4 * i) * 65536];
            s += v[i]; s2 += v[i] * v[i];
        }
        s  += __shfl_xor_sync(0xffffffffu, s, 1);
        s  += __shfl_xor_sync(0xffffffffu, s, 2);
        s2 += __shfl_xor_sync(0xffffffffu, s2, 1);
        s2 += __shfl_xor_sync(0xffffffffu, s2, 2);
        float mean = s * (1.f / 256.f);
        float inv  = rsqrtf(s2 * (1.f / 256.f) - mean * mean + 1e-5f);
        #pragma unroll
        for (int i = 0; i < 64; i++) {
            int c = cb + 4 * i;
            float y = (v[i] - mean) * inv * pre_g[c] + pre_b[c];
            s_an[n0 * PA + c] = bfr(y);
        }
    }
    __syncthreads();

    // mma thread mapping
    const int g      = lane >> 2;
    const int tq     = (lane & 3) * 2;
    const int lane15 = lane & 15;
    const int lhi8   = (lane & 16) ? 8 : 0;
    const int brow   = (lane & 7) + lhi8;
    const int bk     = (lane & 8) ? 8 : 0;
    const int m0     = (warp & 1) * 32;     // 2-way m split
    const int nh4    = warp >> 1;           // 4-way n split

    // per-warp staging slots (2 stages)
    char* qslot0 = stg + (0 * 8 + warp) * 1536;
    char* qslot1 = stg + (1 * 8 + warp) * 1536;

    // ---------- phase 2: 4 passes of (qkv HMMA -> reg epilogue -> HMMA attention) ----------
    #pragma unroll 1
    for (int p = 0; p < 4; p++) {
        float acc[48];
        #pragma unroll
        for (int i = 0; i < 48; i++) acc[i] = 0.f;

        const uint4* gwf = g_wqf4 + p * 6144 + lane;

        // prologue: stage ksteps 0 and 1
        #pragma unroll
        for (int jp = 0; jp < 3; jp++)
            cp16s(qslot0 + jp * 512 + lane * 16, gwf + ((0 * 4 + nh4) * 3 + jp) * 32);
        cp_commit();
        #pragma unroll
        for (int jp = 0; jp < 3; jp++)
            cp16s(qslot1 + jp * 512 + lane * 16, gwf + ((1 * 4 + nh4) * 3 + jp) * 32);
        cp_commit();

        #pragma unroll 2
        for (int kstep = 0; kstep < 16; kstep++) {
            char* cur = (kstep & 1) ? qslot1 : qslot0;
            if (kstep == 15) cp_wait0(); else cp_wait1();

            uint4 Bf0 = *(const uint4*)(cur + 0 * 512 + lane * 16);
            uint4 Bf1 = *(const uint4*)(cur + 1 * 512 + lane * 16);
            uint4 Bf2 = *(const uint4*)(cur + 2 * 512 + lane * 16);

            uint32_t Af[2][4];
            #pragma unroll
            for (int mf = 0; mf < 2; mf++)
                ldsm4(Af[mf], an_b +
                    (((m0 + mf * 16 + lane15) * PA + kstep * 16 + lhi8) << 1));

            // refill this stage with kstep+2 before the MMAs
            if (kstep < 14) {
                #pragma unroll
                for (int jp = 0; jp < 3; jp++)
                    cp16s(cur + jp * 512 + lane * 16,
                          gwf + (((kstep + 2) * 4 + nh4) * 3 + jp) * 32);
                cp_commit();
            }

            #pragma unroll
            for (int mf = 0; mf < 2; mf++) {
                mma16816(&acc[(mf * 6 + 0) * 4], Af[mf][0], Af[mf][1], Af[mf][2], Af[mf][3], Bf0.x, Bf0.y);
                mma16816(&acc[(mf * 6 + 1) * 4], Af[mf][0], Af[mf][1], Af[mf][2], Af[mf][3], Bf0.z, Bf0.w);
                mma16816(&acc[(mf * 6 + 2) * 4], Af[mf][0], Af[mf][1], Af[mf][2], Af[mf][3], Bf1.x, Bf1.y);
                mma16816(&acc[(mf * 6 + 3) * 4], Af[mf][0], Af[mf][1], Af[mf][2], Af[mf][3], Bf1.z, Bf1.w);
                mma16816(&acc[(mf * 6 + 4) * 4], Af[mf][0], Af[mf][1], Af[mf][2], Af[mf][3], Bf2.x, Bf2.y);
                mma16816(&acc[(mf * 6 + 5) * 4], Af[mf][0], Af[mf][1], Af[mf][2], Af[mf][3], Bf2.z, Bf2.w);
            }
        }
        __syncthreads();   // all warps done reading staging before tile writes

        // ---- register epilogue: bias + l2norm (quad shuffles) -> bf16 tiles ----
        #pragma unroll
        for (int bi = 0; bi < 3; bi++) {
            const int blk = nh4 * 3 + bi;   // 0..3 q heads, 4..7 k heads, 8..11 v heads
            const int jj0 = bi * 2;
            #pragma unroll
            for (int mf = 0; mf < 2; mf++) {
                float tv[2][4];
                #pragma unroll
                for (int jj = 0; jj < 2; jj++) {
                    int nl = nh4 * 48 + (jj0 + jj) * 8 + tq;
                    int gcol = (nl >> 6) * 256 + p * 64 + (nl & 63);
                    float b0 = qkv_b[gcol], b1 = qkv_b[gcol + 1];
                    int ai = (mf * 6 + jj0 + jj) * 4;
                    tv[jj][0] = acc[ai + 0] + b0;
                    tv[jj][1] = acc[ai + 1] + b1;
                    tv[jj][2] = acc[ai + 2] + b0;
                    tv[jj][3] = acc[ai + 3] + b1;
                }
                if (blk < 8) {
                    float s0 = tv[0][0]*tv[0][0] + tv[0][1]*tv[0][1]
                             + tv[1][0]*tv[1][0] + tv[1][1]*tv[1][1];
                    float s1 = tv[0][2]*tv[0][2] + tv[0][3]*tv[0][3]
                             + tv[1][2]*tv[1][2] + tv[1][3]*tv[1][3];
                    s0 += __shfl_xor_sync(0xffffffffu, s0, 1);
                    s0 += __shfl_xor_sync(0xffffffffu, s0, 2);
                    s1 += __shfl_xor_sync(0xffffffffu, s1, 1);
                    s1 += __shfl_xor_sync(0xffffffffu, s1, 2);
                    // q gets log2(e) folded in; k plain
                    float sc = (blk < 4) ? LOG2E : 1.f;
                    float r0s = sc / fmaxf(sqrtf(s0), 1e-12f);
                    float r1s = sc / fmaxf(sqrtf(s1), 1e-12f);
                    int head = blk & 3;
                    uint32_t base = (blk < 4) ? qt_b : kt_b;
                    stsm4(base + (((head * 64 + m0 + mf * 16 + lane15) * PQK + lhi8) << 1),
                          pack2(tv[0][0] * r0s, tv[0][1] * r0s),
                          pack2(tv[0][2] * r1s, tv[0][3] * r1s),
                          pack2(tv[1][0] * r0s, tv[1][1] * r0s),
                          pack2(tv[1][2] * r1s, tv[1][3] * r1s));
                } else {
                    int hv = blk - 8;
                    int rl = m0 + mf * 16 + g, rh = rl + 8;
                    #pragma unroll
                    for (int jj = 0; jj < 2; jj++) {
                        int dv = jj * 8 + tq;
                        uint16_t* vp = s_vt + (hv * 16 + dv) * PVT;
                        vp[rl]       = bfr(tv[jj][0]);
                        vp[PVT + rl] = bfr(tv[jj][1]);
                        vp[rh]       = bfr(tv[jj][2]);
                        vp[PVT + rh] = bfr(tv[jj][3]);
                    }
                }
            }
        }
        __syncthreads();

        // ---- HMMA attention: warp -> (head wh, row-half mh) ----
        {
            const int wh = warp >> 1, mh = warp & 1;
            const uint2* gbf = g_biasf + ((p * 4 + wh) * 4) * 256 + lane;

            uint32_t kb0[8], kb1[8];
            #pragma unroll
            for (int jp = 0; jp < 4; jp++) {
                uint32_t r[4];
                ldsm4(r, kt_b + (((wh * 64 + jp * 16 + brow) * PQK + bk) << 1));
                kb0[2 * jp] = r[0]; kb1[2 * jp] = r[1];
                kb0[2 * jp + 1] = r[2]; kb1[2 * jp + 1] = r[3];
            }
            uint32_t vb0[4][2], vb1[4][2];
            #pragma unroll
            for (int ks = 0; ks < 4; ks++) {
                uint32_t r[4];
                ldsm4(r, vt_b + (((wh * 16 + brow) * PVT + ks * 16 + bk) << 1));
                vb0[ks][0] = r[0]; vb1[ks][0] = r[1];
                vb0[ks][1] = r[2]; vb1[ks][1] = r[3];
            }

            #pragma unroll
            for (int t = 0; t < 2; t++) {
                int r = mh * 32 + t * 16;
                // fragment-layout bias (pre-scaled by log2e): 8 coalesced LDG.64
                uint2 bfj[8];
                #pragma unroll
                for (int j = 0; j < 8; j++)
                    bfj[j] = __ldg(gbf + ((mh * 2 + t) * 8 + j) * 32);

                uint32_t qa[4];
                ldsm4(qa, qt_b + (((wh * 64 + r + lane15) * PQK + lhi8) << 1));

                float Sc[8][4];
                #pragma unroll
                for (int j = 0; j < 8; j++) {
                    float2 f0 = unpack2(bfj[j].x);
                    float2 f1 = unpack2(bfj[j].y);
                    Sc[j][0] = f0.x; Sc[j][1] = f0.y;
                    Sc[j][2] = f1.x; Sc[j][3] = f1.y;
                }
                #pragma unroll
                for (int j = 0; j < 8; j++)
                    mma16816(Sc[j], qa[0], qa[1], qa[2], qa[3], kb0[j], kb1[j]);

                float su0 = 0.f, su1 = 0.f;
                #pragma unroll
                for (int j = 0; j < 8; j++) {
                    Sc[j][0] = ex2f(Sc[j][0]);
                    Sc[j][1] = ex2f(Sc[j][1]);
                    Sc[j][2] = ex2f(Sc[j][2]);
                    Sc[j][3] = ex2f(Sc[j][3]);
                    su0 += Sc[j][0] + Sc[j][1];
                    su1 += Sc[j][2] + Sc[j][3];
                }
                su0 += __shfl_xor_sync(0xffffffffu, su0, 1);
                su0 += __shfl_xor_sync(0xffffffffu, su0, 2);
                su1 += __shfl_xor_sync(0xffffffffu, su1, 1);
                su1 += __shfl_xor_sync(0xffffffffu, su1, 2);
                float inv0 = 1.f / su0, inv1 = 1.f / su1;

                // PV with unnormalized P; normalize output (row-linear)
                float Oc[2][4];
                #pragma unroll
                for (int nt = 0; nt < 2; nt++)
                    #pragma unroll
                    for (int i = 0; i < 4; i++) Oc[nt][i] = 0.f;

                #pragma unroll
                for (int ks = 0; ks < 4; ks++) {
                    uint32_t pa0 = pack2(Sc[2 * ks][0],     Sc[2 * ks][1]);
                    uint32_t pa1 = pack2(Sc[2 * ks][2],     Sc[2 * ks][3]);
                    uint32_t pa2 = pack2(Sc[2 * ks + 1][0], Sc[2 * ks + 1][1]);
                    uint32_t pa3 = pack2(Sc[2 * ks + 1][2], Sc[2 * ks + 1][3]);
                    #pragma unroll
                    for (int nt = 0; nt < 2; nt++)
                        mma16816(Oc[nt], pa0, pa1, pa2, pa3, vb0[ks][nt], vb1[ks][nt]);
                }

                int hc = (p * 4 + wh) * 16;
                stsm4(ab_b + (((r + lane15) * PA + hc + lhi8) << 1),
                      pack2(Oc[0][0] * inv0, Oc[0][1] * inv0),
                      pack2(Oc[0][2] * inv1, Oc[0][3] * inv1),
                      pack2(Oc[1][0] * inv0, Oc[1][1] * inv0),
                      pack2(Oc[1][2] * inv1, Oc[1][3] * inv1));
            }
        }
        __syncthreads();
    }

    // ---------- phase 3: proj HMMA (cp.async staged B, zero-sync mainloop) ----------
    float acc[64];
    #pragma unroll
    for (int i = 0; i < 64; i++) acc[i] = 0.f;

    {
        char* pslot0 = stg + (0 * 8 + warp) * 2048;
        char* pslot1 = stg + (1 * 8 + warp) * 2048;
        const uint4* gpf = g_wpf4 + lane;

        #pragma unroll
        for (int jp = 0; jp < 4; jp++)
            cp16s(pslot0 + jp * 512 + lane * 16, gpf + ((0 * 4 + nh4) * 4 + jp) * 32);
        cp_commit();
        #pragma unroll
        for (int jp = 0; jp < 4; jp++)
            cp16s(pslot1 + jp * 512 + lane * 16, gpf + ((1 * 4 + nh4) * 4 + jp) * 32);
        cp_commit();

        #pragma unroll 2
        for (int kb = 0; kb < 16; kb++) {
            char* cur = (kb & 1) ? pslot1 : pslot0;
            if (kb == 15) cp_wait0(); else cp_wait1();

            uint4 Bf0 = *(const uint4*)(cur + 0 * 512 + lane * 16);
            uint4 Bf1 = *(const uint4*)(cur + 1 * 512 + lane * 16);
            uint4 Bf2 = *(const uint4*)(cur + 2 * 512 + lane * 16);
            uint4 Bf3 = *(const uint4*)(cur + 3 * 512 + lane * 16);

            uint32_t Af[2][4];
            #pragma unroll
            for (int mf = 0; mf < 2; mf++)
                ldsm4(Af[mf], ab_b + (((m0 + mf * 16 + lane15) * PA + kb * 16 + lhi8) << 1));

            if (kb < 14) {
                #pragma unroll
                for (int jp = 0; jp < 4; jp++)
                    cp16s(cur + jp * 512 + lane * 16,
                          gpf + (((kb + 2) * 4 + nh4) * 4 + jp) * 32);
                cp_commit();
            }

            #pragma unroll
            for (int mf = 0; mf < 2; mf++) {
                mma16816(&acc[(mf * 8 + 0) * 4], Af[mf][0], Af[mf][1], Af[mf][2], Af[mf][3], Bf0.x, Bf0.y);
                mma16816(&acc[(mf * 8 + 1) * 4], Af[mf][0], Af[mf][1], Af[mf][2], Af[mf][3], Bf0.z, Bf0.w);
                mma16816(&acc[(mf * 8 + 2) * 4], Af[mf][0], Af[mf][1], Af[mf][2], Af[mf][3], Bf1.x, Bf1.y);
                mma16816(&acc[(mf * 8 + 3) * 4], Af[mf][0], Af[mf][1], Af[mf][2], Af[mf][3], Bf1.z, Bf1.w);
                mma16816(&acc[(mf * 8 + 4) * 4], Af[mf][0], Af[mf][1], Af[mf][2], Af[mf][3], Bf2.x, Bf2.y);
                mma16816(&acc[(mf * 8 + 5) * 4], Af[mf][0], Af[mf][1], Af[mf][2], Af[mf][3], Bf2.z, Bf2.w);
                mma16816(&acc[(mf * 8 + 6) * 4], Af[mf][0], Af[mf][1], Af[mf][2], Af[mf][3], Bf3.x, Bf3.y);
                mma16816(&acc[(mf * 8 + 7) * 4], Af[mf][0], Af[mf][1], Af[mf][2], Af[mf][3], Bf3.z, Bf3.w);
            }
        }
    }

    // ---------- phase 4: t = proj + bias + x (regs); post-LN; scatter out ----------
    {
        int rows[4], xo[4];
        #pragma unroll
        for (int mf = 0; mf < 2; mf++) {
            rows[mf * 2 + 0] = m0 + mf * 16 + g;
            rows[mf * 2 + 1] = m0 + mf * 16 + g + 8;
        }
        #pragma unroll
        for (int i = 0; i < 4; i++) xo[i] = (rows[i] >> 3) * 256 + (rows[i] & 7);

        float rs[4], rs2[4];
        #pragma unroll
        for (int i = 0; i < 4; i++) { rs[i] = 0.f; rs2[i] = 0.f; }

        #pragma unroll
        for (int mf = 0; mf < 2; mf++)
            #pragma unroll
            for (int j = 0; j < 8; j++) {
                int c = nh4 * 64 + j * 8 + tq;
                int ai = (mf * 8 + j) * 4;
                float pb0 = proj_b[c], pb1 = proj_b[c + 1];
                acc[ai + 0] += pb0 + Xb[(size_t)c * 65536 + xo[mf * 2]];
                acc[ai + 1] += pb1 + Xb[(size_t)(c + 1) * 65536 + xo[mf * 2]];
                acc[ai + 2] += pb0 + Xb[(size_t)c * 65536 + xo[mf * 2 + 1]];
                acc[ai + 3] += pb1 + Xb[(size_t)(c + 1) * 65536 + xo[mf * 2 + 1]];
                rs[mf * 2]      += acc[ai + 0] + acc[ai + 1];
                rs2[mf * 2]     += acc[ai + 0] * acc[ai + 0] + acc[ai + 1] * acc[ai + 1];
                rs[mf * 2 + 1]  += acc[ai + 2] + acc[ai + 3];
                rs2[mf * 2 + 1] += acc[ai + 2] * acc[ai + 2] + acc[ai + 3] * acc[ai + 3];
            }
        #pragma unroll
        for (int i = 0; i < 4; i++) {
            rs[i]  += __shfl_xor_sync(0xffffffffu, rs[i], 1);
            rs[i]  += __shfl_xor_sync(0xffffffffu, rs[i], 2);
            rs2[i] += __shfl_xor_sync(0xffffffffu, rs2[i], 1);
            rs2[i] += __shfl_xor_sync(0xffffffffu, rs2[i], 2);
        }
        if (tq == 0) {
            #pragma unroll
            for (int i = 0; i < 4; i++)
                s_red[rows[i]][nh4] = make_float2(rs[i], rs2[i]);
        }
        __syncthreads();
        if (tid < 64) {
            float ts = 0.f, ts2 = 0.f;
            #pragma unroll
            for (int q4 = 0; q4 < 4; q4++) {
                float2 a = s_red[tid][q4];
                ts += a.x; ts2 += a.y;
            }
            float mean = ts * (1.f / 256.f);
            s_m[tid] = mean;
            s_i[tid] = rsqrtf(ts2 * (1.f / 256.f) - mean * mean + 1e-5f);
        }
        __syncthreads();

        float mm[4], ii[4];
        #pragma unroll
        for (int i = 0; i < 4; i++) { mm[i] = s_m[rows[i]]; ii[i] = s_i[rows[i]]; }

        #pragma unroll
        for (int mf = 0; mf < 2; mf++)
            #pragma unroll
            for (int j = 0; j < 8; j++) {
                int c = nh4 * 64 + j * 8 + tq;
                int ai = (mf * 8 + j) * 4;
                float pg0 = post_g[c], pg1 = post_g[c + 1];
                float pbb0 = post_b[c], pbb1 = post_b[c + 1];
                int rlo = mf * 2, rhi = mf * 2 + 1;
                float t00 = acc[ai + 0], t01 = acc[ai + 1];
                float t10 = acc[ai + 2], t11 = acc[ai + 3];
                Ob[(size_t)c * 65536 + xo[rlo]]       = t00 + (t00 - mm[rlo]) * ii[rlo] * pg0 + pbb0;
                Ob[(size_t)(c + 1) * 65536 + xo[rlo]] = t01 + (t01 - mm[rlo]) * ii[rlo] * pg1 + pbb1;
                Ob[(size_t)c * 65536 + xo[rhi]]       = t10 + (t10 - mm[rhi]) * ii[rhi] * pg0 + pbb0;
                Ob[(size_t)(c + 1) * 65536 + xo[rhi]] = t11 + (t11 - mm[rhi]) * ii[rhi] * pg1 + pbb1;
            }
    }
}

extern "C" void kernel_launch(void* const* d_in, const int* in_sizes, int n_in,
                              void* d_out, int out_size) {
    const float* X      = (const float*)d_in[0];
    const float* pre_g  = (const float*)d_in[1];
    const float* pre_b  = (const float*)d_in[2];
    const float* post_g = (const float*)d_in[3];
    const float* post_b = (const float*)d_in[4];
    const float* qkv_w  = (const float*)d_in[5];
    const float* qkv_b  = (const float*)d_in[6];
    const float* proj_w = (const float*)d_in[7];
    const float* proj_b = (const float*)d_in[8];
    const float* rtab   = (const float*)d_in[9];
    const int*   ridx   = (const int*)d_in[10];
    float* out = (float*)d_out;

    const int smem_bytes = SMEM_FLOATS * 4;   // 103,936 B -> 2 CTAs/SM
    cudaFuncSetAttribute(window_attn_kernel,
                         cudaFuncAttributeMaxDynamicSharedMemorySize, smem_bytes);

    prep_bias_frag<<<64, 256>>>(rtab, ridx);
    prep_wq_frag4<<<96, 256>>>(qkv_w);
    prep_wp_frag4<<<32, 256>>>(proj_w);
    window_attn_kernel<<<2048, 256, smem_bytes>>>(
        X, pre_g, pre_b, post_g, post_b, qkv_b, proj_b, out);
}

// round 17
// speedup vs baseline: 1.0647x; 1.0647x over previous
#include <cuda_runtime.h>
#include <cuda_bf16.h>
#include <cstdint>

#define HEADS 16
#define NW 64
#define CH 256
#define PA 264      // pitch (halves) bf16 activation buffers [64 x 256]
#define PQK 24      // pitch (halves) q/k head tiles [64 x 16]
#define PVT 72      // pitch (halves) vT head tiles [16 x 64]
#define LOG2E 1.4426950408889634f

// smem float offsets
#define OFF_AN 0        // s_an: bf16 [64][264] = 8448 fl
#define OFF_AB 8448     // s_ab: bf16 [64][264] = 8448 fl
#define OFF_R  16896    // tiles: q 6144h + k 6144h + vT 4608h = 16896h = 8448 fl
#define OFF_MI 25344    // s_m[64], s_i[64]
#define OFF_RED 25472   // s_red float2[64][4] = 512 fl
#define SMEM_FLOATS 25984

__device__ uint2 g_biasf[HEADS * 4 * 8 * 32];       // [h][rowtile(4)][j(8)][lane] C-frag bias (x log2e)
__device__ uint4 g_wqf4[4 * 8 * 2 * 4 * 3 * 32];    // [p][kb][ks][nh4][jp][lane] B-fragment pairs
__device__ uint4 g_wpf4[16 * 4 * 4 * 32];           // [kb][nh4][jp][lane] B-fragment pairs

__device__ __forceinline__ uint32_t pk2(float lo, float hi) {
    __nv_bfloat162 h = __floats2bfloat162_rn(lo, hi);
    return *(uint32_t*)&h;
}
__global__ void prep_bias_frag(const float* __restrict__ table,
                               const int* __restrict__ ridx) {
    int t = blockIdx.x * blockDim.x + threadIdx.x;
    if (t >= 16384) return;
    int lane = t & 31;
    int r = t >> 5;
    int j = r & 7; r >>= 3;
    int rt = r & 3; r >>= 2;
    int h = r;
    int g = lane >> 2, tq = (lane & 3) * 2;
    int row0 = rt * 16 + g, row1 = row0 + 8, col = j * 8 + tq;
    float b00 = table[ridx[row0 * 64 + col] * HEADS + h] * LOG2E;
    float b01 = table[ridx[row0 * 64 + col + 1] * HEADS + h] * LOG2E;
    float b10 = table[ridx[row1 * 64 + col] * HEADS + h] * LOG2E;
    float b11 = table[ridx[row1 * 64 + col + 1] * HEADS + h] * LOG2E;
    uint2 v;
    v.x = pk2(b00, b01);
    v.y = pk2(b10, b11);
    g_biasf[t] = v;
}
__global__ void prep_wq_frag4(const float* __restrict__ qkv_w) {
    int t = blockIdx.x * blockDim.x + threadIdx.x;
    if (t >= 24576) return;
    int lane = t & 31;
    int r = t >> 5;
    int jp = r % 3; r /= 3;
    int nh4 = r & 3; r >>= 2;
    int ks = r & 1; r >>= 1;
    int kb = r & 7; r >>= 3;
    int p = r;
    int g = lane >> 2, tq = (lane & 3) * 2;
    int k0 = kb * 32 + ks * 16 + tq;
    uint4 v;
    {
        int n = nh4 * 48 + (2 * jp) * 8 + g;
        int gcol = (n >> 6) * 256 + p * 64 + (n & 63);
        v.x = pk2(qkv_w[(size_t)k0 * 768 + gcol],       qkv_w[(size_t)(k0 + 1) * 768 + gcol]);
        v.y = pk2(qkv_w[(size_t)(k0 + 8) * 768 + gcol], qkv_w[(size_t)(k0 + 9) * 768 + gcol]);
    }
    {
        int n = nh4 * 48 + (2 * jp + 1) * 8 + g;
        int gcol = (n >> 6) * 256 + p * 64 + (n & 63);
        v.z = pk2(qkv_w[(size_t)k0 * 768 + gcol],       qkv_w[(size_t)(k0 + 1) * 768 + gcol]);
        v.w = pk2(qkv_w[(size_t)(k0 + 8) * 768 + gcol], qkv_w[(size_t)(k0 + 9) * 768 + gcol]);
    }
    g_wqf4[t] = v;
}
__global__ void prep_wp_frag4(const float* __restrict__ proj_w) {
    int t = blockIdx.x * blockDim.x + threadIdx.x;
    if (t >= 8192) return;
    int lane = t & 31;
    int r = t >> 5;
    int jp = r & 3; r >>= 2;
    int nh4 = r & 3; r >>= 2;
    int kb = r;
    int g = lane >> 2, tq = (lane & 3) * 2;
    int k0 = kb * 16 + tq;
    uint4 v;
    {
        int n = nh4 * 64 + (2 * jp) * 8 + g;
        v.x = pk2(proj_w[(size_t)k0 * 256 + n],       proj_w[(size_t)(k0 + 1) * 256 + n]);
        v.y = pk2(proj_w[(size_t)(k0 + 8) * 256 + n], proj_w[(size_t)(k0 + 9) * 256 + n]);
    }
    {
        int n = nh4 * 64 + (2 * jp + 1) * 8 + g;
        v.z = pk2(proj_w[(size_t)k0 * 256 + n],       proj_w[(size_t)(k0 + 1) * 256 + n]);
        v.w = pk2(proj_w[(size_t)(k0 + 8) * 256 + n], proj_w[(size_t)(k0 + 9) * 256 + n]);
    }
    g_wpf4[t] = v;
}

__device__ __forceinline__ uint32_t SAu(const void* p) {
    return (uint32_t)__cvta_generic_to_shared(p);
}
__device__ __forceinline__ void ldsm4(uint32_t* r, uint32_t a) {
    asm volatile("ldmatrix.sync.aligned.m8n8.x4.shared.b16 {%0,%1,%2,%3}, [%4];"
        : "=r"(r[0]), "=r"(r[1]), "=r"(r[2]), "=r"(r[3]) : "r"(a));
}
__device__ __forceinline__ void stsm4(uint32_t a, uint32_t r0, uint32_t r1,
                                      uint32_t r2, uint32_t r3) {
    asm volatile("stmatrix.sync.aligned.m8n8.x4.shared.b16 [%0], {%1,%2,%3,%4};"
        :: "r"(a), "r"(r0), "r"(r1), "r"(r2), "r"(r3) : "memory");
}
__device__ __forceinline__ void mma16816(float* c, uint32_t a0, uint32_t a1,
                                         uint32_t a2, uint32_t a3,
                                         uint32_t b0, uint32_t b1) {
    asm volatile("mma.sync.aligned.m16n8k16.row.col.f32.bf16.bf16.f32 "
        "{%0,%1,%2,%3}, {%4,%5,%6,%7}, {%8,%9}, {%0,%1,%2,%3};"
        : "+f"(c[0]), "+f"(c[1]), "+f"(c[2]), "+f"(c[3])
        : "r"(a0), "r"(a1), "r"(a2), "r"(a3), "r"(b0), "r"(b1));
}
__device__ __forceinline__ uint32_t pack2(float lo, float hi) {
    __nv_bfloat162 h = __floats2bfloat162_rn(lo, hi);
    return *(uint32_t*)&h;
}
__device__ __forceinline__ float2 unpack2(uint32_t u) {
    __nv_bfloat162 h = *(__nv_bfloat162*)&u;
    return make_float2(__bfloat162float(h.x), __bfloat162float(h.y));
}
__device__ __forceinline__ uint16_t bfr(float v) {
    __nv_bfloat16 h = __float2bfloat16(v);
    return *(uint16_t*)&h;
}
__device__ __forceinline__ float ex2f(float x) {
    float y;
    asm("ex2.approx.ftz.f32 %0, %1;" : "=f"(y) : "f"(x));
    return y;
}

__global__ __launch_bounds__(256, 2)
void window_attn_kernel(const float* __restrict__ X,
                        const float* __restrict__ pre_g, const float* __restrict__ pre_b,
                        const float* __restrict__ post_g, const float* __restrict__ post_b,
                        const float* __restrict__ qkv_b, const float* __restrict__ proj_b,
                        float* __restrict__ out) {
    extern __shared__ float sm[];
    uint16_t*  s_an = (uint16_t*)(sm + OFF_AN);
    uint16_t*  s_ab = (uint16_t*)(sm + OFF_AB);
    uint16_t*  s_R  = (uint16_t*)(sm + OFF_R);
    uint16_t*  s_qt = s_R;                 // [4][64][24]
    uint16_t*  s_kt = s_R + 6144;          // [4][64][24]
    uint16_t*  s_vt = s_R + 12288;         // [4][16][72]
    float*     s_m  = sm + OFF_MI;
    float*     s_i  = sm + OFF_MI + 64;
    float2 (*s_red)[4] = (float2(*)[4])(sm + OFF_RED);

    const uint32_t an_b = SAu(s_an);
    const uint32_t ab_b = SAu(s_ab);
    const uint32_t qt_b = SAu(s_qt);
    const uint32_t kt_b = SAu(s_kt);
    const uint32_t vt_b = SAu(s_vt);

    const int w    = blockIdx.x;
    const int b    = w >> 10;
    const int hi   = (w >> 5) & 31;
    const int wi   = w & 31;
    const int tid  = threadIdx.x;
    const int lane = tid & 31;
    const int warp = tid >> 5;

    const float* Xb = X + (size_t)b * (CH * 65536) + hi * 8 * 256 + wi * 8;
    float*       Ob = out + (size_t)b * (CH * 65536) + hi * 8 * 256 + wi * 8;

    // ---------- phase 0: pre-LN from global, X kept in registers ----------
    {
        const int n0 = tid >> 2;
        const int cb = tid & 3;
        float v[64];
        float s = 0.f, s2 = 0.f;
        const float* Xt = Xb + (n0 >> 3) * 256 + (n0 & 7);
        #pragma unroll
        for (int i = 0; i < 64; i++) {
            v[i] = Xt[(size_t)(cb + 4 * i) * 65536];
            s += v[i]; s2 += v[i] * v[i];
        }
        s  += __shfl_xor_sync(0xffffffffu, s, 1);
        s  += __shfl_xor_sync(0xffffffffu, s, 2);
        s2 += __shfl_xor_sync(0xffffffffu, s2, 1);
        s2 += __shfl_xor_sync(0xffffffffu, s2, 2);
        float mean = s * (1.f / 256.f);
        float inv  = rsqrtf(s2 * (1.f / 256.f) - mean * mean + 1e-5f);
        #pragma unroll
        for (int i = 0; i < 64; i++) {
            int c = cb + 4 * i;
            float y = (v[i] - mean) * inv * pre_g[c] + pre_b[c];
            s_an[n0 * PA + c] = bfr(y);
        }
    }
    __syncthreads();

    // mma thread mapping (R12/R14 layout)
    const int g      = lane >> 2;
    const int tq     = (lane & 3) * 2;
    const int lane15 = lane & 15;
    const int lhi8   = (lane & 16) ? 8 : 0;
    const int brow   = (lane & 7) + lhi8;
    const int bk     = (lane & 8) ? 8 : 0;
    const int m0     = (warp & 1) * 32;     // 2-way m split
    const int nh4    = warp >> 1;           // 4-way n split

    // cross-pass prefetched B group (pass 0 kstep 0)
    uint4 Ba[3], Bb[3];
    {
        const uint4* gw0 = g_wqf4 + lane;
        #pragma unroll
        for (int jp = 0; jp < 3; jp++)
            Ba[jp] = __ldg(gw0 + ((0 * 4 + nh4) * 3 + jp) * 32);
    }

    // ---------- phase 2: 4 passes of (qkv HMMA -> reg epilogue -> HMMA attention) ----------
    #pragma unroll 1
    for (int p = 0; p < 4; p++) {
        float acc[48];
        #pragma unroll
        for (int i = 0; i < 48; i++) acc[i] = 0.f;

        const uint4* gwf = g_wqf4 + p * 6144 + lane;

        #pragma unroll 1
        for (int kb = 0; kb < 8; kb++) {
            // fetch ks=1 group of current kb
            #pragma unroll
            for (int jp = 0; jp < 3; jp++)
                Bb[jp] = __ldg(gwf + (((kb * 2 + 1) * 4 + nh4) * 3 + jp) * 32);

            uint32_t Af[2][4];
            #pragma unroll
            for (int mf = 0; mf < 2; mf++)
                ldsm4(Af[mf], an_b +
                    (((m0 + mf * 16 + lane15) * PA + kb * 32 + lhi8) << 1));
            #pragma unroll
            for (int mf = 0; mf < 2; mf++)
                #pragma unroll
                for (int jp = 0; jp < 3; jp++) {
                    mma16816(&acc[(mf * 6 + 2 * jp) * 4],
                             Af[mf][0], Af[mf][1], Af[mf][2], Af[mf][3],
                             Ba[jp].x, Ba[jp].y);
                    mma16816(&acc[(mf * 6 + 2 * jp + 1) * 4],
                             Af[mf][0], Af[mf][1], Af[mf][2], Af[mf][3],
                             Ba[jp].z, Ba[jp].w);
                }

            // fetch next kb ks=0 group
            if (kb < 7) {
                #pragma unroll
                for (int jp = 0; jp < 3; jp++)
                    Ba[jp] = __ldg(gwf + ((((kb + 1) * 2) * 4 + nh4) * 3 + jp) * 32);
            }
            #pragma unroll
            for (int mf = 0; mf < 2; mf++)
                ldsm4(Af[mf], an_b +
                    (((m0 + mf * 16 + lane15) * PA + kb * 32 + 16 + lhi8) << 1));
            #pragma unroll
            for (int mf = 0; mf < 2; mf++)
                #pragma unroll
                for (int jp = 0; jp < 3; jp++) {
                    mma16816(&acc[(mf * 6 + 2 * jp) * 4],
                             Af[mf][0], Af[mf][1], Af[mf][2], Af[mf][3],
                             Bb[jp].x, Bb[jp].y);
                    mma16816(&acc[(mf * 6 + 2 * jp + 1) * 4],
                             Af[mf][0], Af[mf][1], Af[mf][2], Af[mf][3],
                             Bb[jp].z, Bb[jp].w);
                }
        }

        // prefetch next pass's first B group (covered by epilogue + attention)
        if (p < 3) {
            const uint4* gwn = g_wqf4 + (p + 1) * 6144 + lane;
            #pragma unroll
            for (int jp = 0; jp < 3; jp++)
                Ba[jp] = __ldg(gwn + ((0 * 4 + nh4) * 3 + jp) * 32);
        }

        // ---- register epilogue: bias + l2norm (quad shuffles) -> bf16 tiles ----
        #pragma unroll
        for (int bi = 0; bi < 3; bi++) {
            const int blk = nh4 * 3 + bi;   // 0..3 q heads, 4..7 k heads, 8..11 v heads
            const int jj0 = bi * 2;
            #pragma unroll
            for (int mf = 0; mf < 2; mf++) {
                float tv[2][4];
                #pragma unroll
                for (int jj = 0; jj < 2; jj++) {
                    int nl = nh4 * 48 + (jj0 + jj) * 8 + tq;
                    int gcol = (nl >> 6) * 256 + p * 64 + (nl & 63);
                    float b0 = qkv_b[gcol], b1 = qkv_b[gcol + 1];
                    int ai = (mf * 6 + jj0 + jj) * 4;
                    tv[jj][0] = acc[ai + 0] + b0;
                    tv[jj][1] = acc[ai + 1] + b1;
                    tv[jj][2] = acc[ai + 2] + b0;
                    tv[jj][3] = acc[ai + 3] + b1;
                }
                if (blk < 8) {
                    float s0 = tv[0][0]*tv[0][0] + tv[0][1]*tv[0][1]
                             + tv[1][0]*tv[1][0] + tv[1][1]*tv[1][1];
                    float s1 = tv[0][2]*tv[0][2] + tv[0][3]*tv[0][3]
                             + tv[1][2]*tv[1][2] + tv[1][3]*tv[1][3];
                    s0 += __shfl_xor_sync(0xffffffffu, s0, 1);
                    s0 += __shfl_xor_sync(0xffffffffu, s0, 2);
                    s1 += __shfl_xor_sync(0xffffffffu, s1, 1);
                    s1 += __shfl_xor_sync(0xffffffffu, s1, 2);
                    // q gets log2(e) folded in; k plain
                    float sc = (blk < 4) ? LOG2E : 1.f;
                    float r0s = sc / fmaxf(sqrtf(s0), 1e-12f);
                    float r1s = sc / fmaxf(sqrtf(s1), 1e-12f);
                    int head = blk & 3;
                    uint32_t base = (blk < 4) ? qt_b : kt_b;
                    stsm4(base + (((head * 64 + m0 + mf * 16 + lane15) * PQK + lhi8) << 1),
                          pack2(tv[0][0] * r0s, tv[0][1] * r0s),
                          pack2(tv[0][2] * r1s, tv[0][3] * r1s),
                          pack2(tv[1][0] * r0s, tv[1][1] * r0s),
                          pack2(tv[1][2] * r1s, tv[1][3] * r1s));
                } else {
                    int hv = blk - 8;
                    int rl = m0 + mf * 16 + g, rh = rl + 8;
                    #pragma unroll
                    for (int jj = 0; jj < 2; jj++) {
                        int dv = jj * 8 + tq;
                        uint16_t* vp = s_vt + (hv * 16 + dv) * PVT;
                        vp[rl]       = bfr(tv[jj][0]);
                        vp[PVT + rl] = bfr(tv[jj][1]);
                        vp[rh]       = bfr(tv[jj][2]);
                        vp[PVT + rh] = bfr(tv[jj][3]);
                    }
                }
            }
        }
        __syncthreads();

        // ---- HMMA attention: warp -> (head wh, row-half mh) ----
        {
            const int wh = warp >> 1, mh = warp & 1;
            const uint2* gbf = g_biasf + ((p * 4 + wh) * 4) * 256 + lane;

            uint32_t kb0[8], kb1[8];
            #pragma unroll
            for (int jp = 0; jp < 4; jp++) {
                uint32_t r[4];
                ldsm4(r, kt_b + (((wh * 64 + jp * 16 + brow) * PQK + bk) << 1));
                kb0[2 * jp] = r[0]; kb1[2 * jp] = r[1];
                kb0[2 * jp + 1] = r[2]; kb1[2 * jp + 1] = r[3];
            }
            uint32_t vb0[4][2], vb1[4][2];
            #pragma unroll
            for (int ks = 0; ks < 4; ks++) {
                uint32_t r[4];
                ldsm4(r, vt_b + (((wh * 16 + brow) * PVT + ks * 16 + bk) << 1));
                vb0[ks][0] = r[0]; vb1[ks][0] = r[1];
                vb0[ks][1] = r[2]; vb1[ks][1] = r[3];
            }

            #pragma unroll
            for (int t = 0; t < 2; t++) {
                int r = mh * 32 + t * 16;
                // fragment-layout bias (pre-scaled by log2e): 8 coalesced LDG.64
                uint2 bfj[8];
                #pragma unroll
                for (int j = 0; j < 8; j++)
                    bfj[j] = __ldg(gbf + ((mh * 2 + t) * 8 + j) * 32);

                uint32_t qa[4];
                ldsm4(qa, qt_b + (((wh * 64 + r + lane15) * PQK + lhi8) << 1));

                float Sc[8][4];
                #pragma unroll
                for (int j = 0; j < 8; j++) {
                    float2 f0 = unpack2(bfj[j].x);
                    float2 f1 = unpack2(bfj[j].y);
                    Sc[j][0] = f0.x; Sc[j][1] = f0.y;
                    Sc[j][2] = f1.x; Sc[j][3] = f1.y;
                }
                #pragma unroll
                for (int j = 0; j < 8; j++)
                    mma16816(Sc[j], qa[0], qa[1], qa[2], qa[3], kb0[j], kb1[j]);

                float su0 = 0.f, su1 = 0.f;
                #pragma unroll
                for (int j = 0; j < 8; j++) {
                    Sc[j][0] = ex2f(Sc[j][0]);
                    Sc[j][1] = ex2f(Sc[j][1]);
                    Sc[j][2] = ex2f(Sc[j][2]);
                    Sc[j][3] = ex2f(Sc[j][3]);
                    su0 += Sc[j][0] + Sc[j][1];
                    su1 += Sc[j][2] + Sc[j][3];
                }
                su0 += __shfl_xor_sync(0xffffffffu, su0, 1);
                su0 += __shfl_xor_sync(0xffffffffu, su0, 2);
                su1 += __shfl_xor_sync(0xffffffffu, su1, 1);
                su1 += __shfl_xor_sync(0xffffffffu, su1, 2);
                float inv0 = 1.f / su0, inv1 = 1.f / su1;

                // PV with unnormalized P; normalize the output (row-linear)
                float Oc[2][4];
                #pragma unroll
                for (int nt = 0; nt < 2; nt++)
                    #pragma unroll
                    for (int i = 0; i < 4; i++) Oc[nt][i] = 0.f;

                #pragma unroll
                for (int ks = 0; ks < 4; ks++) {
                    uint32_t pa0 = pack2(Sc[2 * ks][0],     Sc[2 * ks][1]);
                    uint32_t pa1 = pack2(Sc[2 * ks][2],     Sc[2 * ks][3]);
                    uint32_t pa2 = pack2(Sc[2 * ks + 1][0], Sc[2 * ks + 1][1]);
                    uint32_t pa3 = pack2(Sc[2 * ks + 1][2], Sc[2 * ks + 1][3]);
                    #pragma unroll
                    for (int nt = 0; nt < 2; nt++)
                        mma16816(Oc[nt], pa0, pa1, pa2, pa3, vb0[ks][nt], vb1[ks][nt]);
                }

                int hc = (p * 4 + wh) * 16;
                stsm4(ab_b + (((r + lane15) * PA + hc + lhi8) << 1),
                      pack2(Oc[0][0] * inv0, Oc[0][1] * inv0),
                      pack2(Oc[0][2] * inv1, Oc[0][3] * inv1),
                      pack2(Oc[1][0] * inv0, Oc[1][1] * inv0),
                      pack2(Oc[1][2] * inv1, Oc[1][3] * inv1));
            }
        }
        __syncthreads();
    }

    // ---------- phase 3: proj HMMA (uint4 B fragments from L2, pipelined, zero-sync) ----------
    float acc[64];
    #pragma unroll
    for (int i = 0; i < 64; i++) acc[i] = 0.f;

    {
        uint4 B[2][4];
        #pragma unroll
        for (int jp = 0; jp < 4; jp++)
            B[0][jp] = __ldg(g_wpf4 + ((0 * 4 + nh4) * 4 + jp) * 32 + lane);

        #pragma unroll 2
        for (int kb = 0; kb < 16; kb++) {
            if (kb < 15) {
                #pragma unroll
                for (int jp = 0; jp < 4; jp++)
                    B[(kb + 1) & 1][jp] =
                        __ldg(g_wpf4 + (((kb + 1) * 4 + nh4) * 4 + jp) * 32 + lane);
            }
            uint32_t Af[2][4];
            #pragma unroll
            for (int mf = 0; mf < 2; mf++)
                ldsm4(Af[mf], ab_b + (((m0 + mf * 16 + lane15) * PA + kb * 16 + lhi8) << 1));
            #pragma unroll
            for (int mf = 0; mf < 2; mf++)
                #pragma unroll
                for (int jp = 0; jp < 4; jp++) {
                    mma16816(&acc[(mf * 8 + 2 * jp) * 4],
                             Af[mf][0], Af[mf][1], Af[mf][2], Af[mf][3],
                             B[kb & 1][jp].x, B[kb & 1][jp].y);
                    mma16816(&acc[(mf * 8 + 2 * jp + 1) * 4],
                             Af[mf][0], Af[mf][1], Af[mf][2], Af[mf][3],
                             B[kb & 1][jp].z, B[kb & 1][jp].w);
                }
        }
    }

    // ---------- phase 4: t = proj + bias + x (regs); post-LN; scatter out ----------
    {
        int rows[4], xo[4];
        #pragma unroll
        for (int mf = 0; mf < 2; mf++) {
            rows[mf * 2 + 0] = m0 + mf * 16 + g;
            rows[mf * 2 + 1] = m0 + mf * 16 + g + 8;
        }
        #pragma unroll
        for (int i = 0; i < 4; i++) xo[i] = (rows[i] >> 3) * 256 + (rows[i] & 7);

        float rs[4], rs2[4];
        #pragma unroll
        for (int i = 0; i < 4; i++) { rs[i] = 0.f; rs2[i] = 0.f; }

        #pragma unroll
        for (int mf = 0; mf < 2; mf++)
            #pragma unroll
            for (int j = 0; j < 8; j++) {
                int c = nh4 * 64 + j * 8 + tq;
                int ai = (mf * 8 + j) * 4;
                float pb0 = proj_b[c], pb1 = proj_b[c + 1];
                acc[ai + 0] += pb0 + Xb[(size_t)c * 65536 + xo[mf * 2]];
                acc[ai + 1] += pb1 + Xb[(size_t)(c + 1) * 65536 + xo[mf * 2]];
                acc[ai + 2] += pb0 + Xb[(size_t)c * 65536 + xo[mf * 2 + 1]];
                acc[ai + 3] += pb1 + Xb[(size_t)(c + 1) * 65536 + xo[mf * 2 + 1]];
                rs[mf * 2]      += acc[ai + 0] + acc[ai + 1];
                rs2[mf * 2]     += acc[ai + 0] * acc[ai + 0] + acc[ai + 1] * acc[ai + 1];
                rs[mf * 2 + 1]  += acc[ai + 2] + acc[ai + 3];
                rs2[mf * 2 + 1] += acc[ai + 2] * acc[ai + 2] + acc[ai + 3] * acc[ai + 3];
            }
        #pragma unroll
        for (int i = 0; i < 4; i++) {
            rs[i]  += __shfl_xor_sync(0xffffffffu, rs[i], 1);
            rs[i]  += __shfl_xor_sync(0xffffffffu, rs[i], 2);
            rs2[i] += __shfl_xor_sync(0xffffffffu, rs2[i], 1);
            rs2[i] += __shfl_xor_sync(0xffffffffu, rs2[i], 2);
        }
        if (tq == 0) {
            #pragma unroll
            for (int i = 0; i < 4; i++)
                s_red[rows[i]][nh4] = make_float2(rs[i], rs2[i]);
        }
        __syncthreads();
        if (tid < 64) {
            float ts = 0.f, ts2 = 0.f;
            #pragma unroll
            for (int q4 = 0; q4 < 4; q4++) {
                float2 a = s_red[tid][q4];
                ts += a.x; ts2 += a.y;
            }
            float mean = ts * (1.f / 256.f);
            s_m[tid] = mean;
            s_i[tid] = rsqrtf(ts2 * (1.f / 256.f) - mean * mean + 1e-5f);
        }
        __syncthreads();

        float mm[4], ii[4];
        #pragma unroll
        for (int i = 0; i < 4; i++) { mm[i] = s_m[rows[i]]; ii[i] = s_i[rows[i]]; }

        #pragma unroll
        for (int mf = 0; mf < 2; mf++)
            #pragma unroll
            for (int j = 0; j < 8; j++) {
                int c = nh4 * 64 + j * 8 + tq;
                int ai = (mf * 8 + j) * 4;
                float pg0 = post_g[c], pg1 = post_g[c + 1];
                float pbb0 = post_b[c], pbb1 = post_b[c + 1];
                int rlo = mf * 2, rhi = mf * 2 + 1;
                float t00 = acc[ai + 0], t01 = acc[ai + 1];
                float t10 = acc[ai + 2], t11 = acc[ai + 3];
                Ob[(size_t)c * 65536 + xo[rlo]]       = t00 + (t00 - mm[rlo]) * ii[rlo] * pg0 + pbb0;
                Ob[(size_t)(c + 1) * 65536 + xo[rlo]] = t01 + (t01 - mm[rlo]) * ii[rlo] * pg1 + pbb1;
                Ob[(size_t)c * 65536 + xo[rhi]]       = t10 + (t10 - mm[rhi]) * ii[rhi] * pg0 + pbb0;
                Ob[(size_t)(c + 1) * 65536 + xo[rhi]] = t11 + (t11 - mm[rhi]) * ii[rhi] * pg1 + pbb1;
            }
    }
}

extern "C" void kernel_launch(void* const* d_in, const int* in_sizes, int n_in,
                              void* d_out, int out_size) {
    const float* X      = (const float*)d_in[0];
    const float* pre_g  = (const float*)d_in[1];
    const float* pre_b  = (const float*)d_in[2];
    const float* post_g = (const float*)d_in[3];
    const float* post_b = (const float*)d_in[4];
    const float* qkv_w  = (const float*)d_in[5];
    const float* qkv_b  = (const float*)d_in[6];
    const float* proj_w = (const float*)d_in[7];
    const float* proj_b = (const float*)d_in[8];
    const float* rtab   = (const float*)d_in[9];
    const int*   ridx   = (const int*)d_in[10];
    float* out = (float*)d_out;

    const int smem_bytes = SMEM_FLOATS * 4;   // 103,936 B -> 2 CTAs/SM
    cudaFuncSetAttribute(window_attn_kernel,
                         cudaFuncAttributeMaxDynamicSharedMemorySize, smem_bytes);

    prep_bias_frag<<<64, 256>>>(rtab, ridx);
    prep_wq_frag4<<<96, 256>>>(qkv_w);
    prep_wp_frag4<<<32, 256>>>(proj_w);
    window_attn_kernel<<<2048, 256, smem_bytes>>>(
        X, pre_g, pre_b, post_g, post_b, qkv_b, proj_b, out);
}